// round 12
// baseline (speedup 1.0000x reference)
#include <cuda_runtime.h>
#include <cuda_fp16.h>
#include <cstdint>

// Dendrite: out[b,d] = sum_{v=1..255} lin_w[v-1] * prod_{s: bit(7-s) of v} p_s + lin_b,
//   p_s = sigmoid(k*(w*x-q)).
// v = hi*16+lo. res[o] = Phi(o)^T W Plo(o), W[hi][lo] = c[hi*16+lo] (c[0]=0).
// Inner contraction inner[o][hi] = sum_lo Plo[o][lo]*W[hi][lo] done on TENSOR
// CORES: per warp, A = Plo [32 outputs x 16 lo] (f16), B = W^T [16 lo x 16 hi]
// (f16), 4x mma.m16n8k16 with f32 accumulation. Epilogue: per-lane Phi table
// (fp32) dotted with its row of inner.
// Warp = one batch row x 32 dendrites (lane = d).

static constexpr int B = 8192;
static constexpr int D = 32;
static constexpr int S = 8;

__device__ __forceinline__ float fast_sigmoid_prehalved(float ah) {
    // sigmoid(a) = 0.5*tanh(a/2)+0.5 ; caller supplies a/2.
    float t;
    asm("tanh.approx.f32 %0, %1;" : "=f"(t) : "f"(ah));
    return fmaf(0.5f, t, 0.5f);
}

__device__ __forceinline__ void mma16816(float c[4],
                                         uint32_t a0, uint32_t a1,
                                         uint32_t a2, uint32_t a3,
                                         uint32_t b0, uint32_t b1) {
    asm volatile(
        "mma.sync.aligned.m16n8k16.row.col.f32.f16.f16.f32 "
        "{%0,%1,%2,%3}, {%4,%5,%6,%7}, {%8,%9}, {%0,%1,%2,%3};"
        : "+f"(c[0]), "+f"(c[1]), "+f"(c[2]), "+f"(c[3])
        : "r"(a0), "r"(a1), "r"(a2), "r"(a3), "r"(b0), "r"(b1));
}

// Per-warp scratch: first used as A (32 rows x 8 half2 = 1KB), then as C
// (32 rows x 20 f32, pad to dodge bank conflicts). Union via max size.
struct WarpScratch { float c[32][20]; };   // 2560 B; A aliases the front 1KB

__global__ __launch_bounds__(128)
void dendrite_kernel(const float* __restrict__ x,      // [B, 1, S]
                     const float* __restrict__ k,      // [D, S]
                     const float* __restrict__ w,      // [D, S]
                     const float* __restrict__ q,      // [D, S]
                     const float* __restrict__ lin_w,  // [1, 255]
                     const float* __restrict__ lin_b,  // [1]
                     float* __restrict__ out)          // [B, 1, D] -> b*D + d
{
    __shared__ __align__(16) uint32_t sWh2[128];  // h2 #i = (c[2i], c[2i+1])
    __shared__ float sA[S][D];                    // [s][d] = 0.5*k*w
    __shared__ float sC[S][D];                    // [s][d] = -0.5*k*q
    __shared__ __align__(16) WarpScratch scr[4];

    const int tid = threadIdx.x;   // 128 threads
    {
        // W table as half2 pairs along lo: h2 #i = (c[2i], c[2i+1])
        const float cE = (tid == 0) ? 0.0f : lin_w[2 * tid - 1];
        const float cO = lin_w[2 * tid];          // c[2i+1] = lin_w[2i]
        const __half2 h = __floats2half2_rn(cE, cO);
        sWh2[tid] = *reinterpret_cast<const uint32_t*>(&h);
#pragma unroll
        for (int i = tid; i < 256; i += 128) {
            const int dd = i >> 3, ss = i & 7;    // i = d*8 + s, flat [D,S]
            const float kh = 0.5f * k[i];
            sA[ss][dd] = kh * w[i];
            sC[ss][dd] = -kh * q[i];
        }
    }
    __syncthreads();

    const int lane = tid & 31;                // lane = d = output row o
    const int warp = tid >> 5;                // 4 warps/block, 1 batch row each
    const int b = blockIdx.x * 4 + warp;
    const int r = lane >> 2;                  // fragment row group 0..7
    const int m = lane & 3;                   // fragment col group 0..3

    // B fragments (uniform per d? no — uniform across ALL warps; load once)
    // B[k=lo][n=hi] = W[hi][lo]; lane: b0b1 = W[row hi=r][lo pair m],
    // b2b3 = lo pair m+4. Frag B0: hi rows 0..7 (n=r); B1: hi rows 8..15.
    const uint32_t b0_lo = sWh2[r * 8 + m];
    const uint32_t b0_hi = sWh2[r * 8 + m + 4];
    const uint32_t b1_lo = sWh2[(r + 8) * 8 + m];
    const uint32_t b1_hi = sWh2[(r + 8) * 8 + m + 4];

    // x row (8 floats, uniform across warp -> broadcast LDG.128)
    const float4* xp = reinterpret_cast<const float4*>(x + b * S);
    const float4 xa = xp[0], xb = xp[1];
    const float xs[8] = {xa.x, xa.y, xa.z, xa.w, xb.x, xb.y, xb.z, xb.w};

    // Sigmoids p0..p7 (fp32)
    float p[8];
#pragma unroll
    for (int s = 0; s < 8; ++s)
        p[s] = fast_sigmoid_prehalved(fmaf(sA[s][lane], xs[s], sC[s][lane]));

    // Plo[16]: lo bit0<->p7, bit1<->p6, bit2<->p5, bit3<->p4.
    // Evens E[j] (j = lo/2, bits: p6,p5,p4), odds = E[j]*p7. Pack (E, E*p7).
    {
        const float p4f = p[4], p5f = p[5], p6f = p[6], p7f = p[7];
        float E[8];
        E[0] = 1.0f;       E[1] = p6f;
        E[2] = p5f;        E[3] = p5f * p6f;
        E[4] = p4f;        E[5] = p4f * p6f;
        E[6] = p4f * p5f;  E[7] = E[3] * p4f;
        uint32_t* arow = reinterpret_cast<uint32_t*>(scr[warp].c[0]) + lane * 8;
        uint4 v0, v1;
        uint32_t pk[8];
#pragma unroll
        for (int j = 0; j < 8; ++j) {
            const __half2 h = __floats2half2_rn(E[j], E[j] * p7f);
            pk[j] = *reinterpret_cast<const uint32_t*>(&h);
        }
        v0.x = pk[0]; v0.y = pk[1]; v0.z = pk[2]; v0.w = pk[3];
        v1.x = pk[4]; v1.y = pk[5]; v1.z = pk[6]; v1.w = pk[7];
        reinterpret_cast<uint4*>(arow)[0] = v0;   // 2x STS.128, row = lane (32B)
        reinterpret_cast<uint4*>(arow)[1] = v1;
    }
    __syncwarp();

    // A fragments from smem (row-major 16x16, rows = outputs):
    // a0:(row r, lo pair m)  a1:(row r+8, m)  a2:(row r, m+4)  a3:(row r+8, m+4)
    const uint32_t* Abuf = reinterpret_cast<const uint32_t*>(scr[warp].c[0]);
    const uint32_t a0_0 = Abuf[r * 8 + m];            // A0: output rows 0..15
    const uint32_t a0_1 = Abuf[(r + 8) * 8 + m];
    const uint32_t a0_2 = Abuf[r * 8 + m + 4];
    const uint32_t a0_3 = Abuf[(r + 8) * 8 + m + 4];
    const uint32_t a1_0 = Abuf[(r + 16) * 8 + m];     // A1: output rows 16..31
    const uint32_t a1_1 = Abuf[(r + 24) * 8 + m];
    const uint32_t a1_2 = Abuf[(r + 16) * 8 + m + 4];
    const uint32_t a1_3 = Abuf[(r + 24) * 8 + m + 4];

    float c00[4] = {0, 0, 0, 0}, c01[4] = {0, 0, 0, 0};
    float c10[4] = {0, 0, 0, 0}, c11[4] = {0, 0, 0, 0};
    mma16816(c00, a0_0, a0_1, a0_2, a0_3, b0_lo, b0_hi);  // rows 0-15, hi 0-7
    mma16816(c01, a0_0, a0_1, a0_2, a0_3, b1_lo, b1_hi);  // rows 0-15, hi 8-15
    mma16816(c10, a1_0, a1_1, a1_2, a1_3, b0_lo, b0_hi);  // rows 16-31, hi 0-7
    mma16816(c11, a1_0, a1_1, a1_2, a1_3, b1_lo, b1_hi);  // rows 16-31, hi 8-15
    __syncwarp();

    // Scatter C fragments: c0,c1 -> (row r, hi 2m,2m+1); c2,c3 -> (row r+8).
    {
        float (*C)[20] = scr[warp].c;
        *reinterpret_cast<float2*>(&C[r][2 * m])           = {c00[0], c00[1]};
        *reinterpret_cast<float2*>(&C[r + 8][2 * m])       = {c00[2], c00[3]};
        *reinterpret_cast<float2*>(&C[r][8 + 2 * m])       = {c01[0], c01[1]};
        *reinterpret_cast<float2*>(&C[r + 8][8 + 2 * m])   = {c01[2], c01[3]};
        *reinterpret_cast<float2*>(&C[r + 16][2 * m])      = {c10[0], c10[1]};
        *reinterpret_cast<float2*>(&C[r + 24][2 * m])      = {c10[2], c10[3]};
        *reinterpret_cast<float2*>(&C[r + 16][8 + 2 * m])  = {c11[0], c11[1]};
        *reinterpret_cast<float2*>(&C[r + 24][8 + 2 * m])  = {c11[2], c11[3]};
    }
    __syncwarp();

    // Epilogue: lane o reads inner[o][0..15], dots with Phi table.
    // hi bit0<->p3, bit1<->p2, bit2<->p1, bit3<->p0.
    float inn[16];
    {
        const float2* crow = reinterpret_cast<const float2*>(scr[warp].c[lane]);
#pragma unroll
        for (int j = 0; j < 8; ++j) {
            const float2 v = crow[j];
            inn[2 * j] = v.x; inn[2 * j + 1] = v.y;
        }
    }
    float Phi[16];
    {
        const float p0f = p[0], p1f = p[1], p2f = p[2], p3f = p[3];
        Phi[0] = 1.0f;          Phi[1] = p3f;
        Phi[2] = p2f;           Phi[3] = p2f * p3f;
        Phi[4] = p1f;           Phi[5] = p1f * p3f;
        Phi[6] = p1f * p2f;     Phi[7] = Phi[3] * p1f;
        Phi[8] = p0f;           Phi[9] = p0f * p3f;
        Phi[10] = p0f * p2f;    Phi[11] = Phi[3] * p0f;
        Phi[12] = p0f * p1f;    Phi[13] = Phi[5] * p0f;
        Phi[14] = Phi[6] * p0f; Phi[15] = Phi[7] * p0f;
    }
    float accA = Phi[0] * inn[0];
    float accB = Phi[1] * inn[1];
#pragma unroll
    for (int j = 1; j < 8; ++j) {
        accA = fmaf(Phi[2 * j], inn[2 * j], accA);
        accB = fmaf(Phi[2 * j + 1], inn[2 * j + 1], accB);
    }

    out[b * D + lane] = accA + accB + lin_b[0];
}

extern "C" void kernel_launch(void* const* d_in, const int* in_sizes, int n_in,
                              void* d_out, int out_size) {
    const float* x     = (const float*)d_in[0];
    const float* k     = (const float*)d_in[1];
    const float* w     = (const float*)d_in[2];
    const float* q     = (const float*)d_in[3];
    // d_in[4] = mask (unused: fixed binary-expansion generation rule)
    const float* lin_w = (const float*)d_in[5];
    const float* lin_b = (const float*)d_in[6];
    float* out = (float*)d_out;

    // 128 threads = 4 warps; 1 batch row per warp -> 4 rows/block -> 2048 blocks
    dendrite_kernel<<<B / 4, 128>>>(x, k, w, q, lin_w, lin_b, out);
}

// round 13
// speedup vs baseline: 1.2294x; 1.2294x over previous
#include <cuda_runtime.h>
#include <cuda_fp16.h>
#include <cstdint>

// Dendrite: out[b,d] = sum_{v=1..255} lin_w[v-1] * prod_{s: bit(7-s) of v} p_s + lin_b
// v = hi*16+lo. inner[o][hi] = sum_lo Plo[o][lo]*W[hi][lo] via tensor cores
// (A = Plo 32x16 f16, B = W^T 16x16 f16, 4x mma.m16n8k16, f32 accum).
// Epilogue fully in registers: Phi via shfl.idx of p0..p3, per-row weighted
// partials, shfl.xor butterfly reduction over the fragment m-group.
// A staging uses an XOR swizzle -> conflict-free STS.128 + fragment LDS.

static constexpr int B = 8192;
static constexpr int D = 32;
static constexpr int S = 8;

__device__ __forceinline__ float fast_sigmoid_prehalved(float ah) {
    float t;
    asm("tanh.approx.f32 %0, %1;" : "=f"(t) : "f"(ah));
    return fmaf(0.5f, t, 0.5f);
}

__device__ __forceinline__ void mma16816(float c[4],
                                         uint32_t a0, uint32_t a1,
                                         uint32_t a2, uint32_t a3,
                                         uint32_t b0, uint32_t b1) {
    asm volatile(
        "mma.sync.aligned.m16n8k16.row.col.f32.f16.f16.f32 "
        "{%0,%1,%2,%3}, {%4,%5,%6,%7}, {%8,%9}, {%0,%1,%2,%3};"
        : "+f"(c[0]), "+f"(c[1]), "+f"(c[2]), "+f"(c[3])
        : "r"(a0), "r"(a1), "r"(a2), "r"(a3), "r"(b0), "r"(b1));
}

__device__ __forceinline__ uint32_t sw(uint32_t byte_off) {
    return byte_off ^ ((byte_off >> 3) & 0x70);
}

__global__ __launch_bounds__(128)
void dendrite_kernel(const float* __restrict__ x,      // [B, 1, S]
                     const float* __restrict__ k,      // [D, S]
                     const float* __restrict__ w,      // [D, S]
                     const float* __restrict__ q,      // [D, S]
                     const float* __restrict__ lin_w,  // [1, 255]
                     const float* __restrict__ lin_b,  // [1]
                     float* __restrict__ out)          // [B, 1, D] -> b*D + d
{
    __shared__ __align__(16) char sWb[512];      // swizzled W half2 table
    __shared__ float sA[S][D];                   // [s][d] = 0.5*k*w
    __shared__ float sC[S][D];                   // [s][d] = -0.5*k*q
    __shared__ __align__(16) char sAbuf[4][1024];  // per-warp A staging (swizzled)

    const int tid = threadIdx.x;              // 128 threads
    const int lane = tid & 31;                // lane = d = output row o
    const int warp = tid >> 5;                // 4 warps/block, 1 batch row each
    const int b = blockIdx.x * 4 + warp;

    // x row first (uniform across warp -> broadcast LDG.128)
    const float4* xp = reinterpret_cast<const float4*>(x + b * S);
    const float4 xa = xp[0], xb = xp[1];
    const float xs[8] = {xa.x, xa.y, xa.z, xa.w, xb.x, xb.y, xb.z, xb.w};
    const float bias = lin_b[0];

    {
        // W table as half2 pairs along lo: h2 #i = (c[2i], c[2i+1]), c[0]=0
        const float cE = (tid == 0) ? 0.0f : lin_w[2 * tid - 1];
        const float cO = lin_w[2 * tid];
        const __half2 h = __floats2half2_rn(cE, cO);
        *reinterpret_cast<uint32_t*>(sWb + sw(tid * 4)) =
            *reinterpret_cast<const uint32_t*>(&h);
#pragma unroll
        for (int i = tid; i < 256; i += 128) {
            const int dd = i >> 3, ss = i & 7;    // i = d*8 + s, flat [D,S]
            const float kh = 0.5f * k[i];
            sA[ss][dd] = kh * w[i];
            sC[ss][dd] = -kh * q[i];
        }
    }
    __syncthreads();

    const int r = lane >> 2;                  // fragment row group 0..7
    const int m = lane & 3;                   // fragment col group 0..3

    // B fragments: B[k=lo][n=hi] = W[hi][lo].
    const uint32_t b0_lo = *reinterpret_cast<const uint32_t*>(sWb + sw((r * 8 + m) * 4));
    const uint32_t b0_hi = *reinterpret_cast<const uint32_t*>(sWb + sw((r * 8 + m + 4) * 4));
    const uint32_t b1_lo = *reinterpret_cast<const uint32_t*>(sWb + sw(((r + 8) * 8 + m) * 4));
    const uint32_t b1_hi = *reinterpret_cast<const uint32_t*>(sWb + sw(((r + 8) * 8 + m + 4) * 4));

    // Sigmoids p0..p7 (fp32)
    float p[8];
#pragma unroll
    for (int s = 0; s < 8; ++s)
        p[s] = fast_sigmoid_prehalved(fmaf(sA[s][lane], xs[s], sC[s][lane]));

    // Plo row (16 f16): lo bit0<->p7, bit1<->p6, bit2<->p5, bit3<->p4.
    {
        const float p4f = p[4], p5f = p[5], p6f = p[6], p7f = p[7];
        float E[8];
        E[0] = 1.0f;       E[1] = p6f;
        E[2] = p5f;        E[3] = p5f * p6f;
        E[4] = p4f;        E[5] = p4f * p6f;
        E[6] = p4f * p5f;  E[7] = E[3] * p4f;
        uint32_t pk[8];
#pragma unroll
        for (int j = 0; j < 8; ++j) {
            const __half2 h = __floats2half2_rn(E[j], E[j] * p7f);
            pk[j] = *reinterpret_cast<const uint32_t*>(&h);
        }
        char* abase = sAbuf[warp];
        const uint32_t off = lane * 32;
        *reinterpret_cast<uint4*>(abase + sw(off))      = {pk[0], pk[1], pk[2], pk[3]};
        *reinterpret_cast<uint4*>(abase + sw(off + 16)) = {pk[4], pk[5], pk[6], pk[7]};
    }
    __syncwarp();

    // A fragments (row-major 16x16 per half): row = output, k-pair j.
    const char* abase = sAbuf[warp];
#define LDA(row, j) (*reinterpret_cast<const uint32_t*>(abase + sw((row) * 32 + (j) * 4)))
    const uint32_t a0_0 = LDA(r, m),      a0_1 = LDA(r + 8, m);
    const uint32_t a0_2 = LDA(r, m + 4),  a0_3 = LDA(r + 8, m + 4);
    const uint32_t a1_0 = LDA(r + 16, m),     a1_1 = LDA(r + 24, m);
    const uint32_t a1_2 = LDA(r + 16, m + 4), a1_3 = LDA(r + 24, m + 4);
#undef LDA

    float c00[4] = {0, 0, 0, 0}, c01[4] = {0, 0, 0, 0};
    float c10[4] = {0, 0, 0, 0}, c11[4] = {0, 0, 0, 0};
    mma16816(c00, a0_0, a0_1, a0_2, a0_3, b0_lo, b0_hi);  // rows 0-15,  hi 0-7
    mma16816(c01, a0_0, a0_1, a0_2, a0_3, b1_lo, b1_hi);  // rows 0-15,  hi 8-15
    mma16816(c10, a1_0, a1_1, a1_2, a1_3, b0_lo, b0_hi);  // rows 16-31, hi 0-7
    mma16816(c11, a1_0, a1_1, a1_2, a1_3, b1_lo, b1_hi);  // rows 16-31, hi 8-15

    // In-register epilogue. Fragment mapping (verified in R12):
    //  c00[0..1]=(row r, hi 2m,2m+1)   c00[2..3]=(row r+8, hi 2m,2m+1)
    //  c01      = same rows, hi 8+2m,8+2m+1 ;  c10/c11 = rows r+16 / r+24.
    // Phi[row][hi]: hi bit0<->p3, bit1<->p2, bit2<->p1, bit3<->p0.
    // For this lane's his {2m,2m+1,8+2m,8+2m+1}: g = (m&1?p2:1)*(m&2?p1:1);
    // weights = {g, g*p3, g*p0, g*p0*p3}.
    float partial[4];
#pragma unroll
    for (int i = 0; i < 4; ++i) {
        const int row = r + 8 * i;
        const float P0 = __shfl_sync(0xffffffffu, p[0], row);
        const float P1 = __shfl_sync(0xffffffffu, p[1], row);
        const float P2 = __shfl_sync(0xffffffffu, p[2], row);
        const float P3 = __shfl_sync(0xffffffffu, p[3], row);
        float g = (m & 1) ? P2 : 1.0f;
        if (m & 2) g *= P1;
        float cA0, cA1, cB0, cB1;
        if (i == 0)      { cA0 = c00[0]; cA1 = c00[1]; cB0 = c01[0]; cB1 = c01[1]; }
        else if (i == 1) { cA0 = c00[2]; cA1 = c00[3]; cB0 = c01[2]; cB1 = c01[3]; }
        else if (i == 2) { cA0 = c10[0]; cA1 = c10[1]; cB0 = c11[0]; cB1 = c11[1]; }
        else             { cA0 = c10[2]; cA1 = c10[3]; cB0 = c11[2]; cB1 = c11[3]; }
        const float tA = fmaf(P3, cA1, cA0);
        const float tB = fmaf(P3, cB1, cB0);
        partial[i] = g * fmaf(P0, tB, tA);
    }

    // Butterfly over the m-group (lanes r*4+{0..3}): totals for rows r+8i.
#pragma unroll
    for (int stage = 1; stage <= 2; stage <<= 1) {
#pragma unroll
        for (int i = 0; i < 4; ++i)
            partial[i] += __shfl_xor_sync(0xffffffffu, partial[i], stage);
    }

    // Lane (r,m) writes output row d = r + 8*m  (32 distinct d's per warp).
    float res = partial[0];
    if (m == 1) res = partial[1];
    else if (m == 2) res = partial[2];
    else if (m == 3) res = partial[3];
    out[b * D + (r + 8 * m)] = res + bias;
}

extern "C" void kernel_launch(void* const* d_in, const int* in_sizes, int n_in,
                              void* d_out, int out_size) {
    const float* x     = (const float*)d_in[0];
    const float* k     = (const float*)d_in[1];
    const float* w     = (const float*)d_in[2];
    const float* q     = (const float*)d_in[3];
    // d_in[4] = mask (unused: fixed binary-expansion generation rule)
    const float* lin_w = (const float*)d_in[5];
    const float* lin_b = (const float*)d_in[6];
    float* out = (float*)d_out;

    // 128 threads = 4 warps; 1 batch row per warp -> 4 rows/block -> 2048 blocks
    dendrite_kernel<<<B / 4, 128>>>(x, k, w, q, lin_w, lin_b, out);
}

// round 14
// speedup vs baseline: 1.2704x; 1.0333x over previous
#include <cuda_runtime.h>
#include <cuda_fp16.h>
#include <cstdint>

// Dendrite: out[b,d] = sum_{v=1..255} lin_w[v-1] * prod_{s: bit(7-s) of v} p_s + lin_b
// v = hi*16+lo. inner[o][hi] = sum_lo Plo[o][lo]*W[hi][lo] via tensor cores
// (A = Plo 32x16 f16, B = W^T 16x16 f16, 4x mma.m16n8k16, f32 accum).
// Epilogue: lane (r,m) computes outer gates p0..p3 for ITS OUTPUT row r+8m
// (lane->row bijection), quad-transposes the raw C packets (16 shfl.xor),
// then all Phi weighting is local fp32 FMA. No shfl.idx, no final select.
// Param tables vectorized to float4 (4 LDS.128/lane total).

static constexpr int B = 8192;
static constexpr int D = 32;
static constexpr int S = 8;

__device__ __forceinline__ float fast_sigmoid_prehalved(float ah) {
    float t;
    asm("tanh.approx.f32 %0, %1;" : "=f"(t) : "f"(ah));
    return fmaf(0.5f, t, 0.5f);
}

__device__ __forceinline__ void mma16816(float c[4],
                                         uint32_t a0, uint32_t a1,
                                         uint32_t a2, uint32_t a3,
                                         uint32_t b0, uint32_t b1) {
    asm volatile(
        "mma.sync.aligned.m16n8k16.row.col.f32.f16.f16.f32 "
        "{%0,%1,%2,%3}, {%4,%5,%6,%7}, {%8,%9}, {%0,%1,%2,%3};"
        : "+f"(c[0]), "+f"(c[1]), "+f"(c[2]), "+f"(c[3])
        : "r"(a0), "r"(a1), "r"(a2), "r"(a3), "r"(b0), "r"(b1));
}

__device__ __forceinline__ uint32_t sw(uint32_t byte_off) {
    return byte_off ^ ((byte_off >> 3) & 0x70);
}

// 4x4 transpose across a quad (lanes share r, m = lane&3): new v[j] = old
// v[m] of quad-lane j. Verified: block-swap (xor 2) then in-block (xor 1).
__device__ __forceinline__ void quad_transpose(float v[4], int m) {
    float x0 = (m & 2) ? v[0] : v[2];
    float r0 = __shfl_xor_sync(0xffffffffu, x0, 2);
    if (m & 2) v[0] = r0; else v[2] = r0;
    float x1 = (m & 2) ? v[1] : v[3];
    float r1 = __shfl_xor_sync(0xffffffffu, x1, 2);
    if (m & 2) v[1] = r1; else v[3] = r1;
    float y0 = (m & 1) ? v[0] : v[1];
    float s0 = __shfl_xor_sync(0xffffffffu, y0, 1);
    if (m & 1) v[0] = s0; else v[1] = s0;
    float y1 = (m & 1) ? v[2] : v[3];
    float s1 = __shfl_xor_sync(0xffffffffu, y1, 1);
    if (m & 1) v[2] = s1; else v[3] = s1;
}

__global__ __launch_bounds__(128)
void dendrite_kernel(const float* __restrict__ x,      // [B, 1, S]
                     const float* __restrict__ k,      // [D, S]
                     const float* __restrict__ w,      // [D, S]
                     const float* __restrict__ q,      // [D, S]
                     const float* __restrict__ lin_w,  // [1, 255]
                     const float* __restrict__ lin_b,  // [1]
                     float* __restrict__ out)          // [B, 1, D] -> b*D + d
{
    __shared__ __align__(16) char sWb[512];        // swizzled W half2 table
    __shared__ __align__(16) float4 sAhi[32];      // A[d][4..7],  A = 0.5*k*w
    __shared__ __align__(16) float4 sChi[32];      // C[d][4..7],  C = -0.5*k*q
    __shared__ __align__(16) float4 sAloP[32];     // A[row(l)][0..3], permuted
    __shared__ __align__(16) float4 sCloP[32];     // C[row(l)][0..3], permuted
    __shared__ __align__(16) char sAbuf[4][1024];  // per-warp A staging

    const int tid = threadIdx.x;              // 128 threads
    const int lane = tid & 31;
    const int warp = tid >> 5;                // 4 warps/block, 1 batch row each
    const int b = blockIdx.x * 4 + warp;

    // x row (uniform across warp -> broadcast LDG.128)
    const float4* xp = reinterpret_cast<const float4*>(x + b * S);
    const float4 xa = xp[0], xb = xp[1];
    const float xs[8] = {xa.x, xa.y, xa.z, xa.w, xb.x, xb.y, xb.z, xb.w};
    const float bias = lin_b[0];

    {
        // W table as half2 pairs along lo: h2 #i = (c[2i], c[2i+1]), c[0]=0
        const float cE = (tid == 0) ? 0.0f : lin_w[2 * tid - 1];
        const float cO = lin_w[2 * tid];
        const __half2 h = __floats2half2_rn(cE, cO);
        *reinterpret_cast<uint32_t*>(sWb + sw(tid * 4)) =
            *reinterpret_cast<const uint32_t*>(&h);

        // param tables: part 0: Ahi, 1: Chi, 2: AloP, 3: CloP
        const int dd = tid & 31;
        const int part = tid >> 5;
        const int s0 = (part < 2) ? 4 : 0;
        const float4 k4 = *reinterpret_cast<const float4*>(k + dd * 8 + s0);
        const float4 w4 = *reinterpret_cast<const float4*>(w + dd * 8 + s0);
        const float4 q4 = *reinterpret_cast<const float4*>(q + dd * 8 + s0);
        float4 Av, Cv;
        Av.x = 0.5f * k4.x * w4.x;  Cv.x = -0.5f * k4.x * q4.x;
        Av.y = 0.5f * k4.y * w4.y;  Cv.y = -0.5f * k4.y * q4.y;
        Av.z = 0.5f * k4.z * w4.z;  Cv.z = -0.5f * k4.z * q4.z;
        Av.w = 0.5f * k4.w * w4.w;  Cv.w = -0.5f * k4.w * q4.w;
        const int pos = 4 * (dd & 7) + (dd >> 3);  // row(pos) == dd
        if (part == 0)      sAhi[dd] = Av;
        else if (part == 1) sChi[dd] = Cv;
        else if (part == 2) sAloP[pos] = Av;
        else                sCloP[pos] = Cv;
    }
    __syncthreads();

    const int r = lane >> 2;                  // fragment row group 0..7
    const int m = lane & 3;                   // fragment col group 0..3

    // B fragments: B[k=lo][n=hi] = W[hi][lo]
    const uint32_t b0_lo = *reinterpret_cast<const uint32_t*>(sWb + sw((r * 8 + m) * 4));
    const uint32_t b0_hi = *reinterpret_cast<const uint32_t*>(sWb + sw((r * 8 + m + 4) * 4));
    const uint32_t b1_lo = *reinterpret_cast<const uint32_t*>(sWb + sw(((r + 8) * 8 + m) * 4));
    const uint32_t b1_hi = *reinterpret_cast<const uint32_t*>(sWb + sw(((r + 8) * 8 + m + 4) * 4));

    // Inner gates p4..p7 for d = lane (feed the A matrix)
    const float4 Ah = sAhi[lane];
    const float4 Ch = sChi[lane];
    const float p4f = fast_sigmoid_prehalved(fmaf(Ah.x, xs[4], Ch.x));
    const float p5f = fast_sigmoid_prehalved(fmaf(Ah.y, xs[5], Ch.y));
    const float p6f = fast_sigmoid_prehalved(fmaf(Ah.z, xs[6], Ch.z));
    const float p7f = fast_sigmoid_prehalved(fmaf(Ah.w, xs[7], Ch.w));

    // Plo row (16 f16): lo bit0<->p7, bit1<->p6, bit2<->p5, bit3<->p4
    {
        float E[8];
        E[0] = 1.0f;       E[1] = p6f;
        E[2] = p5f;        E[3] = p5f * p6f;
        E[4] = p4f;        E[5] = p4f * p6f;
        E[6] = p4f * p5f;  E[7] = E[3] * p4f;
        uint32_t pk[8];
#pragma unroll
        for (int j = 0; j < 8; ++j) {
            const __half2 h = __floats2half2_rn(E[j], E[j] * p7f);
            pk[j] = *reinterpret_cast<const uint32_t*>(&h);
        }
        char* abase = sAbuf[warp];
        const uint32_t off = lane * 32;
        *reinterpret_cast<uint4*>(abase + sw(off))      = {pk[0], pk[1], pk[2], pk[3]};
        *reinterpret_cast<uint4*>(abase + sw(off + 16)) = {pk[4], pk[5], pk[6], pk[7]};
    }

    // Outer gates p0..p3 for THIS LANE'S OUTPUT row = r + 8m (bijection)
    const float4 Al = sAloP[lane];
    const float4 Cl = sCloP[lane];
    const float P0 = fast_sigmoid_prehalved(fmaf(Al.x, xs[0], Cl.x));
    const float P1 = fast_sigmoid_prehalved(fmaf(Al.y, xs[1], Cl.y));
    const float P2 = fast_sigmoid_prehalved(fmaf(Al.z, xs[2], Cl.z));
    const float P3 = fast_sigmoid_prehalved(fmaf(Al.w, xs[3], Cl.w));
    __syncwarp();

    // A fragments (row-major 16x16 per half): row = output d, k-pair j
    const char* abase = sAbuf[warp];
#define LDA(row, j) (*reinterpret_cast<const uint32_t*>(abase + sw((row) * 32 + (j) * 4)))
    const uint32_t a0_0 = LDA(r, m),          a0_1 = LDA(r + 8, m);
    const uint32_t a0_2 = LDA(r, m + 4),      a0_3 = LDA(r + 8, m + 4);
    const uint32_t a1_0 = LDA(r + 16, m),     a1_1 = LDA(r + 24, m);
    const uint32_t a1_2 = LDA(r + 16, m + 4), a1_3 = LDA(r + 24, m + 4);
#undef LDA

    float c00[4] = {0, 0, 0, 0}, c01[4] = {0, 0, 0, 0};
    float c10[4] = {0, 0, 0, 0}, c11[4] = {0, 0, 0, 0};
    mma16816(c00, a0_0, a0_1, a0_2, a0_3, b0_lo, b0_hi);  // rows 0-15,  hi 0-7
    mma16816(c01, a0_0, a0_1, a0_2, a0_3, b1_lo, b1_hi);  // rows 0-15,  hi 8-15
    mma16816(c10, a1_0, a1_1, a1_2, a1_3, b0_lo, b0_hi);  // rows 16-31, hi 0-7
    mma16816(c11, a1_0, a1_1, a1_2, a1_3, b1_lo, b1_hi);  // rows 16-31, hi 8-15

    // Epilogue. Packet i (row r+8i) at this lane: elements
    //   e0 = hi 2m, e1 = hi 2m+1, e2 = hi 8+2m, e3 = hi 8+2m+1.
    // Element vectors across i, transposed within the quad: after transpose,
    // vE[j] = element from quad-lane j for row r+8m (own output row).
    float v0[4] = {c00[0], c00[2], c10[0], c10[2]};
    float v1[4] = {c00[1], c00[3], c10[1], c10[3]};
    float v2[4] = {c01[0], c01[2], c11[0], c11[2]};
    float v3[4] = {c01[1], c01[3], c11[1], c11[3]};
    quad_transpose(v0, m);
    quad_transpose(v1, m);
    quad_transpose(v2, m);
    quad_transpose(v3, m);

    // From lane j: e0 = hi 2j, e1 = hi 2j+1, e2 = hi 8+2j, e3 = hi 8+2j+1.
    // Phi bits: hi bit0<->P3, bit3<->P0, bits1-2 = j -> P2^(j&1)*P1^(j>>1).
    float inn[4];
#pragma unroll
    for (int j = 0; j < 4; ++j) {
        const float tA = fmaf(P3, v1[j], v0[j]);
        const float tB = fmaf(P3, v3[j], v2[j]);
        inn[j] = fmaf(P0, tB, tA);
    }
    const float g12 = P1 * P2;
    float res = fmaf(P2, inn[1], inn[0]);
    res = fmaf(P1, inn[2], res);
    res = fmaf(g12, inn[3], res);

    out[b * D + (r + 8 * m)] = res + bias;
}

extern "C" void kernel_launch(void* const* d_in, const int* in_sizes, int n_in,
                              void* d_out, int out_size) {
    const float* x     = (const float*)d_in[0];
    const float* k     = (const float*)d_in[1];
    const float* w     = (const float*)d_in[2];
    const float* q     = (const float*)d_in[3];
    // d_in[4] = mask (unused: fixed binary-expansion generation rule)
    const float* lin_w = (const float*)d_in[5];
    const float* lin_b = (const float*)d_in[6];
    float* out = (float*)d_out;

    // 128 threads = 4 warps; 1 batch row per warp -> 2048 blocks
    dendrite_kernel<<<B / 4, 128>>>(x, k, w, q, lin_w, lin_b, out);
}